// round 14
// baseline (speedup 1.0000x reference)
#include <cuda_runtime.h>
#include <cuda_bf16.h>
#include <cstdint>
#include <math.h>

#define BGRAPH 64
#define NNODE  256
#define FIN    256
#define OUTF   256
#define DEP    64
#define HID    256
#define G3     768
#define E_EDGES 262144
#define NN_TOT  16384
#define CQ     32   // 32 k-quads of 8 -> k=0..255, all smem-resident as bf16

// ---------------- device scratch (accessed ONLY via symbol inside kernels) ----------------
__device__ __align__(16) float    g_deg [NN_TOT];
__device__ __align__(16) float    g_dinv[NN_TOT];
__device__ __align__(16) float    g_beones[OUTF];
__device__ __align__(16) float    g_Ax  [NN_TOT*OUTF];
__device__ __align__(16) float    g_agg [NN_TOT*OUTF];
__device__ __align__(16) float    g_seqA[NN_TOT*OUTF];
__device__ __align__(16) float    g_seqB[NN_TOT*OUTF];
__device__ __align__(16) float    g_xp  [NN_TOT*G3];
__device__ __align__(16) unsigned g_wb  [3][CQ*G3*4];  // bf16x2-packed w_hh
__device__ __align__(16) float    g_ht  [3*BGRAPH*HID];

// fast gates (ex2.approx-based, rel err ~1e-6)
__device__ __forceinline__ float fsig(float x){
    return __fdividef(1.0f, 1.0f + __expf(-x));
}
__device__ __forceinline__ float ftanh(float x){
    float x2 = fminf(fmaxf(2.0f*x, -30.0f), 30.0f);
    float e2 = __expf(x2);
    return __fdividef(e2 - 1.0f, e2 + 1.0f);
}

// packed f32x2 helpers
#define PACK64(out, lo, hi) \
    asm("mov.b64 %0, {%1, %2};" : "=l"(out) : "r"(lo), "r"(hi))
#define PACK64F(out, lo, hi) \
    asm("mov.b64 %0, {%1, %2};" : "=l"(out) : "f"(lo), "f"(hi))
#define FFMA2(acc, a, b) \
    asm("fma.rn.f32x2 %0, %1, %2, %0;" : "+l"(acc) : "l"(a), "l"(b))

// ---------------- degree ----------------
__global__ void k_deg_init(){ g_deg[blockIdx.x*256+threadIdx.x] = 1.0f; }
__global__ void k_deg_count(const int* __restrict__ eidx){
    int e = blockIdx.x*256+threadIdx.x;
    atomicAdd(&g_deg[eidx[E_EDGES+e]], 1.0f);
}
__global__ void k_dinv_beones(const float* __restrict__ WB){
    if (blockIdx.x < 64){
        int i = blockIdx.x*256+threadIdx.x;
        g_dinv[i] = rsqrtf(g_deg[i]);
    } else {
        int j = threadIdx.x; float s = 0.f;
        for (int k=0;k<DEP;k++) s += WB[j*DEP+k];
        g_beones[j] = s;
    }
}

// ---------------- SGEMM v2: 128x128 tile, 8x8/thread (4+4 split), K=256 ----------------
__global__ void __launch_bounds__(256) k_gemm(const float* __restrict__ Aext, int asel,
                                              const float* __restrict__ B,
                                              const float* __restrict__ bias,
                                              int csel, int N){
    const float* A = Aext ? Aext : (asel == 0 ? (const float*)g_seqA : (const float*)g_seqB);
    float* C = (csel == 0) ? g_Ax : g_xp;
    const int K = 256;
    __shared__ float As[16][128];
    __shared__ float Bs[16][128];
    int bm = blockIdx.y*128, bn = blockIdx.x*128;
    int t = threadIdx.x;
    int tx = t & 15, ty = t >> 4;
    int lr = t >> 1, lk = (t & 1)*8;

    float acc[8][8];
#pragma unroll
    for (int i=0;i<8;i++)
#pragma unroll
        for (int j=0;j<8;j++) acc[i][j]=0.f;

    for (int k0=0;k0<K;k0+=16){
        float4 a0 = *(const float4*)&A[(size_t)(bm+lr)*K + k0 + lk];
        float4 a1 = *(const float4*)&A[(size_t)(bm+lr)*K + k0 + lk + 4];
        float4 b0 = *(const float4*)&B[(size_t)(bn+lr)*K + k0 + lk];
        float4 b1 = *(const float4*)&B[(size_t)(bn+lr)*K + k0 + lk + 4];
        __syncthreads();
        As[lk+0][lr]=a0.x; As[lk+1][lr]=a0.y; As[lk+2][lr]=a0.z; As[lk+3][lr]=a0.w;
        As[lk+4][lr]=a1.x; As[lk+5][lr]=a1.y; As[lk+6][lr]=a1.z; As[lk+7][lr]=a1.w;
        Bs[lk+0][lr]=b0.x; Bs[lk+1][lr]=b0.y; Bs[lk+2][lr]=b0.z; Bs[lk+3][lr]=b0.w;
        Bs[lk+4][lr]=b1.x; Bs[lk+5][lr]=b1.y; Bs[lk+6][lr]=b1.z; Bs[lk+7][lr]=b1.w;
        __syncthreads();
#pragma unroll
        for (int kk=0;kk<16;kk++){
            float4 aA = *(const float4*)&As[kk][ty*4];
            float4 aB = *(const float4*)&As[kk][64 + ty*4];
            float4 bA = *(const float4*)&Bs[kk][tx*4];
            float4 bB = *(const float4*)&Bs[kk][64 + tx*4];
            float ar[8] = {aA.x,aA.y,aA.z,aA.w, aB.x,aB.y,aB.z,aB.w};
            float br[8] = {bA.x,bA.y,bA.z,bA.w, bB.x,bB.y,bB.z,bB.w};
#pragma unroll
            for (int i=0;i<8;i++)
#pragma unroll
                for (int j=0;j<8;j++) acc[i][j] += ar[i]*br[j];
        }
    }
    float4 bvA = make_float4(0.f,0.f,0.f,0.f), bvB = bvA;
    if (bias){
        bvA = *(const float4*)&bias[bn + tx*4];
        bvB = *(const float4*)&bias[bn + 64 + tx*4];
    }
#pragma unroll
    for (int i=0;i<8;i++){
        int ri = (i<4) ? (ty*4 + i) : (64 + ty*4 + i - 4);
        float4 oA, oB;
        oA.x=acc[i][0]+bvA.x; oA.y=acc[i][1]+bvA.y; oA.z=acc[i][2]+bvA.z; oA.w=acc[i][3]+bvA.w;
        oB.x=acc[i][4]+bvB.x; oB.y=acc[i][5]+bvB.y; oB.z=acc[i][6]+bvB.z; oB.w=acc[i][7]+bvB.w;
        *(float4*)&C[(size_t)(bm+ri)*N + bn + tx*4]      = oA;
        *(float4*)&C[(size_t)(bm+ri)*N + bn + 64 + tx*4] = oB;
    }
}

// ---------------- GCN self-loop init of agg ----------------
__global__ void k_self(){
    int idx = blockIdx.x*256+threadIdx.x;
    int i = idx >> 8, j = idx & 255;
    float dv = g_dinv[i];
    g_agg[idx] = dv*dv*ftanh(g_Ax[idx]*g_beones[j]);
}

// ---------------- GCN edge aggregation (global atomics) ----------------
__global__ void __launch_bounds__(256) k_edge(const float* __restrict__ eattr,
                                              const int*   __restrict__ eidx,
                                              const float* __restrict__ WB){
    extern __shared__ float sh[];
    float* WBt   = sh;              // [64][256] k-major
    float* ea_sh = WBt + 64*256;    // [8][64]
    float* snorm = ea_sh + 8*64;    // [8]
    int*   ssrc  = (int*)(snorm+8); // [8]
    int*   sdst  = ssrc + 8;        // [8]

    int t = threadIdx.x;
    for (int idx=t; idx<64*256; idx+=256){
        int j = idx & 255, k = idx >> 8;
        WBt[idx] = WB[j*DEP + k];
    }
    int w = t >> 5, lane = t & 31;
    int base = blockIdx.x*256;

    for (int b=0;b<32;b++){
        __syncthreads();
        int e0 = base + b*8;
        if (t < 8){
            int e = e0 + t;
            int s = eidx[e], d = eidx[E_EDGES+e];
            ssrc[t]=s; sdst[t]=d; snorm[t]=g_dinv[s]*g_dinv[d];
        }
        {
            int e = t >> 5, k2 = (t & 31)*2;
            *(float2*)&ea_sh[e*64+k2] = *(const float2*)&eattr[(size_t)(e0+e)*DEP + k2];
        }
        __syncthreads();

        int   src = ssrc[w], dst = sdst[w];
        float nr  = snorm[w];
        const float* ea = &ea_sh[w*64];
#pragma unroll
        for (int p=0;p<2;p++){
            int j = p*128 + lane*4;
            float4 acc = make_float4(0.f,0.f,0.f,0.f);
#pragma unroll 8
            for (int k=0;k<64;k++){
                float a = ea[k];
                float4 wv = *(const float4*)&WBt[k*256 + j];
                acc.x += a*wv.x; acc.y += a*wv.y; acc.z += a*wv.z; acc.w += a*wv.w;
            }
            float4 ax = *(const float4*)&g_Ax[(size_t)src*256 + j];
            float* ag = &g_agg[(size_t)dst*256 + j];
            atomicAdd(&ag[0], nr*ftanh(ax.x*acc.x));
            atomicAdd(&ag[1], nr*ftanh(ax.y*acc.y));
            atomicAdd(&ag[2], nr*ftanh(ax.z*acc.z));
            atomicAdd(&ag[3], nr*ftanh(ax.w*acc.w));
        }
    }
}

// ---------------- node = tanh(agg/deg + bias) -> g_seqA ----------------
__global__ void k_node(const float* __restrict__ gbias){
    int idx = blockIdx.x*256+threadIdx.x;
    int i = idx >> 8, j = idx & 255;
    g_seqA[idx] = ftanh(g_agg[idx]*__frcp_rn(g_deg[i]) + gbias[j]);
}

// ---------------- pack w_hh -> bf16x2, k-quad layout ----------------
__global__ void k_wtb(const float* __restrict__ whh, int layer){
    int idx = blockIdx.x*256+threadIdx.x;   // over 768*128
    int row = idx >> 7, q = idx & 127;
    int cq = q >> 2, j = q & 3;
    int k0 = cq*8 + 2*j;
    __nv_bfloat162 p = __floats2bfloat162_rn(whh[row*256 + k0], whh[row*256 + k0 + 1]);
    g_wb[layer][(cq*G3 + row)*4 + j] = *(unsigned*)&p;
}

// ---------------- GRU recurrence v6: FFMA2 packed matvec + split local/peer halves ----------------
__device__ __forceinline__ void quad_ffma2(const unsigned* __restrict__ sbw, int c, int tid,
                                           const float* __restrict__ hp,
                                           uint64_t& acc01, uint64_t& acc23){
    uint4  wq = *(const uint4*)&sbw[(c*384 + tid)*4];
    float4 hA = *(const float4*)&hp[c*8];
    float4 hB = *(const float4*)&hp[c*8 + 4];
    uint32_t lx = wq.x << 16, hx = wq.x & 0xffff0000u;
    uint32_t ly = wq.y << 16, hy = wq.y & 0xffff0000u;
    uint32_t lz = wq.z << 16, hz = wq.z & 0xffff0000u;
    uint32_t lw = wq.w << 16, hw = wq.w & 0xffff0000u;
    uint64_t w01, w23, w45, w67, ha01, ha23, hb01, hb23;
    PACK64(w01, lx, hx);  PACK64(w23, ly, hy);
    PACK64(w45, lz, hz);  PACK64(w67, lw, hw);
    PACK64F(ha01, hA.x, hA.y);  PACK64F(ha23, hA.z, hA.w);
    PACK64F(hb01, hB.x, hB.y);  PACK64F(hb23, hB.z, hB.w);
    FFMA2(acc01, w01, ha01);
    FFMA2(acc23, w23, ha23);
    FFMA2(acc01, w45, hb01);
    FFMA2(acc23, w67, hb23);
}

__global__ void __launch_bounds__(384) __cluster_dims__(2,1,1)
k_gru(const float* __restrict__ bhh, int osel, int layer){
    extern __shared__ unsigned sbw[];                // [CQ*384*4] = 196608 B
    __shared__ __align__(16) float h[2][HID];
    __shared__ float gh[3][128];
    __shared__ __align__(8) uint64_t mbar;
    int bx = blockIdx.x;
    int g = bx >> 1, rank = bx & 1;
    int tid = threadIdx.x;
    int band = tid >> 7, idx = tid & 127;
    int row = band*256 + rank*128 + idx;
    int u = rank*128 + idx;
    float* seqout = osel ? g_seqB : g_seqA;
    const unsigned* wl = g_wb[layer];

    uint32_t mbl = (uint32_t)__cvta_generic_to_shared(&mbar);
    uint32_t mbr;
    asm("mapa.shared::cluster.u32 %0, %1, %2;" : "=r"(mbr) : "r"(mbl), "r"(rank^1));
    if (tid == 0)
        asm volatile("mbarrier.init.shared.b64 [%0], 1;" :: "r"(mbl) : "memory");

#pragma unroll 4
    for (int c=0; c<CQ; c++)
        *(uint4*)&sbw[(c*384 + tid)*4] = *(const uint4*)&wl[(c*G3 + row)*4];
    if (tid < HID) h[0][tid] = 0.f;
    float bb = bhh[row];
    const float* xpr = &g_xp[(size_t)g*256*G3];
    asm volatile("barrier.cluster.arrive.aligned;" ::: "memory");
    asm volatile("barrier.cluster.wait.aligned;"  ::: "memory");

    int cl0 = rank*16;          // k-quads covering locally-computed h
    int cp0 = (rank^1)*16;      // k-quads covering peer-delivered h
    int ph = 0;
    for (int s=0; s<256; s++){
        int rp = s & 1, wp = rp ^ 1;
        float x0=0.f, x1=0.f, x2=0.f;
        if (band == 0){
            const float* xr = &xpr[(size_t)s*G3];
            x0 = xr[u]; x1 = xr[256+u]; x2 = xr[512+u];
        }
        const float* hp = h[rp];
        uint64_t acc01 = 0ull, acc23 = 0ull;   // packed {0.f,0.f}
#pragma unroll 4
        for (int c=cl0; c<cl0+16; c++)
            quad_ffma2(sbw, c, tid, hp, acc01, acc23);
        if (s > 0){
            unsigned done = 0;
            while (!done){
                asm volatile("{\n\t.reg .pred p;\n\t"
                    "mbarrier.try_wait.parity.acquire.cluster.shared::cta.b64 p, [%1], %2, 0x989680;\n\t"
                    "selp.b32 %0, 1, 0, p;\n\t}"
                    : "=r"(done) : "r"(mbl), "r"((unsigned)ph) : "memory");
            }
            ph ^= 1;
        }
#pragma unroll 4
        for (int c=cp0; c<cp0+16; c++)
            quad_ffma2(sbw, c, tid, hp, acc01, acc23);
        float a0, a1, a2, a3;
        {
            uint32_t u0,u1,u2,u3;
            asm("mov.b64 {%0, %1}, %2;" : "=r"(u0), "=r"(u1) : "l"(acc01));
            asm("mov.b64 {%0, %1}, %2;" : "=r"(u2), "=r"(u3) : "l"(acc23));
            a0 = __uint_as_float(u0); a1 = __uint_as_float(u1);
            a2 = __uint_as_float(u2); a3 = __uint_as_float(u3);
        }
        gh[band][idx] = a0 + a1 + a2 + a3 + bb;
        __syncthreads();
        if (band == 0){
            float r = fsig(x0 + gh[0][idx]);
            float z = fsig(x1 + gh[1][idx]);
            float n = ftanh(x2 + r*gh[2][idx]);
            float hn = (1.f - z)*n + z*hp[u];
            h[wp][u] = hn;
            uint32_t la = (uint32_t)__cvta_generic_to_shared(&h[wp][u]);
            uint32_t ra;
            asm("mapa.shared::cluster.u32 %0, %1, %2;" : "=r"(ra) : "r"(la), "r"(rank^1));
            asm volatile("st.shared::cluster.f32 [%0], %1;" :: "r"(ra), "f"(hn));
            seqout[(size_t)(g*256+s)*HID + u] = hn;
        }
        __syncthreads();   // all band0 local+remote stores issued before signal
        if (tid == 0 && s < 255)
            asm volatile("mbarrier.arrive.release.cluster.shared::cluster.b64 _, [%0];"
                         :: "r"(mbr) : "memory");
    }
    if (band == 0) g_ht[layer*NN_TOT + g*HID + u] = h[0][u];  // step 255 wrote wp=0
    asm volatile("barrier.cluster.arrive.aligned;" ::: "memory");
    asm volatile("barrier.cluster.wait.aligned;"  ::: "memory");
}

// ---------------- pooling + linear + softmax ----------------
__global__ void __launch_bounds__(256) k_final(const float* __restrict__ linW,
                                               const float* __restrict__ linb,
                                               float* __restrict__ out){
    __shared__ float r0[256], r1[256];
    int g = blockIdx.x, j = threadIdx.x;
    float mx = -1e30f, sm = 0.f;
    const float* seq = &g_seqB[(size_t)g*256*HID];
    for (int s=0;s<256;s++){
        float v = seq[(size_t)s*HID + j];
        mx = fmaxf(mx, v); sm += v;
    }
    float avg = sm * (1.0f/256.0f);
    float h0 = g_ht[0*NN_TOT + g*HID + j];
    float h1 = g_ht[1*NN_TOT + g*HID + j];
    float h2 = g_ht[2*NN_TOT + g*HID + j];
    float p0 = h0*linW[j] + h1*linW[256+j] + h2*linW[512+j] + mx*linW[768+j] + avg*linW[1024+j];
    float p1 = h0*linW[1280+j] + h1*linW[1536+j] + h2*linW[1792+j] + mx*linW[2048+j] + avg*linW[2304+j];
    r0[j] = p0; r1[j] = p1;
    __syncthreads();
    for (int stp=128; stp>0; stp>>=1){
        if (j < stp){ r0[j]+=r0[j+stp]; r1[j]+=r1[j+stp]; }
        __syncthreads();
    }
    if (j == 0){
        float l0 = r0[0] + linb[0], l1 = r1[0] + linb[1];
        float m = fmaxf(l0,l1);
        float e0 = expf(l0-m), e1 = expf(l1-m);
        float inv = 1.0f/(e0+e1);
        out[g*2+0] = e0*inv;
        out[g*2+1] = e1*inv;
    }
}

// ---------------- launch ----------------
extern "C" void kernel_launch(void* const* d_in, const int* in_sizes, int n_in,
                              void* d_out, int out_size){
    const float* x      = (const float*)d_in[0];
    const float* eattr  = (const float*)d_in[1];
    const int*   eidx   = (const int*)  d_in[2];
    const float* WA     = (const float*)d_in[3];
    const float* WB     = (const float*)d_in[4];
    const float* gbias  = (const float*)d_in[5];
    const float* wih[3] = {(const float*)d_in[6],  (const float*)d_in[10], (const float*)d_in[14]};
    const float* whh[3] = {(const float*)d_in[7],  (const float*)d_in[11], (const float*)d_in[15]};
    const float* bih[3] = {(const float*)d_in[8],  (const float*)d_in[12], (const float*)d_in[16]};
    const float* bhh[3] = {(const float*)d_in[9],  (const float*)d_in[13], (const float*)d_in[17]};
    const float* linW   = (const float*)d_in[18];
    const float* linb   = (const float*)d_in[19];
    float* out = (float*)d_out;

    size_t edge_smem = (64*256 + 8*64 + 8)*sizeof(float) + 16*sizeof(int) + 64;
    size_t gru_smem  = (size_t)CQ*384*4*sizeof(unsigned);   // 196608 B
    cudaFuncSetAttribute(k_edge, cudaFuncAttributeMaxDynamicSharedMemorySize, (int)edge_smem);
    cudaFuncSetAttribute(k_gru,  cudaFuncAttributeMaxDynamicSharedMemorySize, (int)gru_smem);

    k_deg_init<<<NN_TOT/256, 256>>>();
    k_deg_count<<<E_EDGES/256, 256>>>(eidx);
    k_dinv_beones<<<65, 256>>>(WB);
    // launch #4 (profiled slot): the Ax SGEMM
    k_gemm<<<dim3(OUTF/128, NN_TOT/128), 256>>>(x, 0, WA, nullptr, 0, OUTF);
    k_self<<<NN_TOT*OUTF/256, 256>>>();
    k_edge<<<1024, 256, edge_smem>>>(eattr, eidx, WB);
    k_node<<<NN_TOT*OUTF/256, 256>>>(gbias);
    for (int l=0;l<3;l++) k_wtb<<<G3*128/256, 256>>>(whh[l], l);

    const int insel[3]  = {0, 1, 0};
    const int outsel[3] = {1, 0, 1};
    for (int l=0;l<3;l++){
        k_gemm<<<dim3(G3/128, NN_TOT/128), 256>>>(nullptr, insel[l], wih[l], bih[l], 1, G3);
        k_gru<<<2*BGRAPH, 384, gru_smem>>>(bhh[l], outsel[l], l);
    }
    k_final<<<BGRAPH, 256>>>(linW, linb, out);
}

// round 15
// speedup vs baseline: 1.1308x; 1.1308x over previous
#include <cuda_runtime.h>
#include <cuda_bf16.h>
#include <cstdint>
#include <math.h>

#define BGRAPH 64
#define NNODE  256
#define FIN    256
#define OUTF   256
#define DEP    64
#define HID    256
#define G3     768
#define E_EDGES 262144
#define NN_TOT  16384
#define CQ     32   // 32 k-quads of 8 -> k=0..255 (16 in regs, 16 in smem)

// ---------------- device scratch (accessed ONLY via symbol inside kernels) ----------------
__device__ __align__(16) float    g_deg [NN_TOT];
__device__ __align__(16) float    g_dinv[NN_TOT];
__device__ __align__(16) float    g_beones[OUTF];
__device__ __align__(16) float    g_Ax  [NN_TOT*OUTF];
__device__ __align__(16) float    g_agg [NN_TOT*OUTF];
__device__ __align__(16) float    g_seqA[NN_TOT*OUTF];
__device__ __align__(16) float    g_seqB[NN_TOT*OUTF];
__device__ __align__(16) float    g_xp  [NN_TOT*G3];
__device__ __align__(16) unsigned g_wb  [3][CQ*G3*4];  // bf16x2-packed w_hh
__device__ __align__(16) float    g_ht  [3*BGRAPH*HID];

// fast gates (ex2.approx-based, rel err ~1e-6)
__device__ __forceinline__ float fsig(float x){
    return __fdividef(1.0f, 1.0f + __expf(-x));
}
__device__ __forceinline__ float ftanh(float x){
    float x2 = fminf(fmaxf(2.0f*x, -30.0f), 30.0f);
    float e2 = __expf(x2);
    return __fdividef(e2 - 1.0f, e2 + 1.0f);
}

// ---------------- degree ----------------
__global__ void k_deg_init(){ g_deg[blockIdx.x*256+threadIdx.x] = 1.0f; }
__global__ void k_deg_count(const int* __restrict__ eidx){
    int e = blockIdx.x*256+threadIdx.x;
    atomicAdd(&g_deg[eidx[E_EDGES+e]], 1.0f);
}
__global__ void k_dinv_beones(const float* __restrict__ WB){
    if (blockIdx.x < 64){
        int i = blockIdx.x*256+threadIdx.x;
        g_dinv[i] = rsqrtf(g_deg[i]);
    } else {
        int j = threadIdx.x; float s = 0.f;
        for (int k=0;k<DEP;k++) s += WB[j*DEP+k];
        g_beones[j] = s;
    }
}

// ---------------- SGEMM v2: 128x128 tile, 8x8/thread (4+4 split), K=256 ----------------
__global__ void __launch_bounds__(256) k_gemm(const float* __restrict__ Aext, int asel,
                                              const float* __restrict__ B,
                                              const float* __restrict__ bias,
                                              int csel, int N){
    const float* A = Aext ? Aext : (asel == 0 ? (const float*)g_seqA : (const float*)g_seqB);
    float* C = (csel == 0) ? g_Ax : g_xp;
    const int K = 256;
    __shared__ float As[16][128];
    __shared__ float Bs[16][128];
    int bm = blockIdx.y*128, bn = blockIdx.x*128;
    int t = threadIdx.x;
    int tx = t & 15, ty = t >> 4;
    int lr = t >> 1, lk = (t & 1)*8;

    float acc[8][8];
#pragma unroll
    for (int i=0;i<8;i++)
#pragma unroll
        for (int j=0;j<8;j++) acc[i][j]=0.f;

    for (int k0=0;k0<K;k0+=16){
        float4 a0 = *(const float4*)&A[(size_t)(bm+lr)*K + k0 + lk];
        float4 a1 = *(const float4*)&A[(size_t)(bm+lr)*K + k0 + lk + 4];
        float4 b0 = *(const float4*)&B[(size_t)(bn+lr)*K + k0 + lk];
        float4 b1 = *(const float4*)&B[(size_t)(bn+lr)*K + k0 + lk + 4];
        __syncthreads();
        As[lk+0][lr]=a0.x; As[lk+1][lr]=a0.y; As[lk+2][lr]=a0.z; As[lk+3][lr]=a0.w;
        As[lk+4][lr]=a1.x; As[lk+5][lr]=a1.y; As[lk+6][lr]=a1.z; As[lk+7][lr]=a1.w;
        Bs[lk+0][lr]=b0.x; Bs[lk+1][lr]=b0.y; Bs[lk+2][lr]=b0.z; Bs[lk+3][lr]=b0.w;
        Bs[lk+4][lr]=b1.x; Bs[lk+5][lr]=b1.y; Bs[lk+6][lr]=b1.z; Bs[lk+7][lr]=b1.w;
        __syncthreads();
#pragma unroll
        for (int kk=0;kk<16;kk++){
            float4 aA = *(const float4*)&As[kk][ty*4];
            float4 aB = *(const float4*)&As[kk][64 + ty*4];
            float4 bA = *(const float4*)&Bs[kk][tx*4];
            float4 bB = *(const float4*)&Bs[kk][64 + tx*4];
            float ar[8] = {aA.x,aA.y,aA.z,aA.w, aB.x,aB.y,aB.z,aB.w};
            float br[8] = {bA.x,bA.y,bA.z,bA.w, bB.x,bB.y,bB.z,bB.w};
#pragma unroll
            for (int i=0;i<8;i++)
#pragma unroll
                for (int j=0;j<8;j++) acc[i][j] += ar[i]*br[j];
        }
    }
    float4 bvA = make_float4(0.f,0.f,0.f,0.f), bvB = bvA;
    if (bias){
        bvA = *(const float4*)&bias[bn + tx*4];
        bvB = *(const float4*)&bias[bn + 64 + tx*4];
    }
#pragma unroll
    for (int i=0;i<8;i++){
        int ri = (i<4) ? (ty*4 + i) : (64 + ty*4 + i - 4);
        float4 oA, oB;
        oA.x=acc[i][0]+bvA.x; oA.y=acc[i][1]+bvA.y; oA.z=acc[i][2]+bvA.z; oA.w=acc[i][3]+bvA.w;
        oB.x=acc[i][4]+bvB.x; oB.y=acc[i][5]+bvB.y; oB.z=acc[i][6]+bvB.z; oB.w=acc[i][7]+bvB.w;
        *(float4*)&C[(size_t)(bm+ri)*N + bn + tx*4]      = oA;
        *(float4*)&C[(size_t)(bm+ri)*N + bn + 64 + tx*4] = oB;
    }
}

// ---------------- GCN self-loop init of agg ----------------
__global__ void k_self(){
    int idx = blockIdx.x*256+threadIdx.x;
    int i = idx >> 8, j = idx & 255;
    float dv = g_dinv[i];
    g_agg[idx] = dv*dv*ftanh(g_Ax[idx]*g_beones[j]);
}

// ---------------- GCN edge aggregation (global atomics) ----------------
__global__ void __launch_bounds__(256) k_edge(const float* __restrict__ eattr,
                                              const int*   __restrict__ eidx,
                                              const float* __restrict__ WB){
    extern __shared__ float sh[];
    float* WBt   = sh;              // [64][256] k-major
    float* ea_sh = WBt + 64*256;    // [8][64]
    float* snorm = ea_sh + 8*64;    // [8]
    int*   ssrc  = (int*)(snorm+8); // [8]
    int*   sdst  = ssrc + 8;        // [8]

    int t = threadIdx.x;
    for (int idx=t; idx<64*256; idx+=256){
        int j = idx & 255, k = idx >> 8;
        WBt[idx] = WB[j*DEP + k];
    }
    int w = t >> 5, lane = t & 31;
    int base = blockIdx.x*256;

    for (int b=0;b<32;b++){
        __syncthreads();
        int e0 = base + b*8;
        if (t < 8){
            int e = e0 + t;
            int s = eidx[e], d = eidx[E_EDGES+e];
            ssrc[t]=s; sdst[t]=d; snorm[t]=g_dinv[s]*g_dinv[d];
        }
        {
            int e = t >> 5, k2 = (t & 31)*2;
            *(float2*)&ea_sh[e*64+k2] = *(const float2*)&eattr[(size_t)(e0+e)*DEP + k2];
        }
        __syncthreads();

        int   src = ssrc[w], dst = sdst[w];
        float nr  = snorm[w];
        const float* ea = &ea_sh[w*64];
#pragma unroll
        for (int p=0;p<2;p++){
            int j = p*128 + lane*4;
            float4 acc = make_float4(0.f,0.f,0.f,0.f);
#pragma unroll 8
            for (int k=0;k<64;k++){
                float a = ea[k];
                float4 wv = *(const float4*)&WBt[k*256 + j];
                acc.x += a*wv.x; acc.y += a*wv.y; acc.z += a*wv.z; acc.w += a*wv.w;
            }
            float4 ax = *(const float4*)&g_Ax[(size_t)src*256 + j];
            float* ag = &g_agg[(size_t)dst*256 + j];
            atomicAdd(&ag[0], nr*ftanh(ax.x*acc.x));
            atomicAdd(&ag[1], nr*ftanh(ax.y*acc.y));
            atomicAdd(&ag[2], nr*ftanh(ax.z*acc.z));
            atomicAdd(&ag[3], nr*ftanh(ax.w*acc.w));
        }
    }
}

// ---------------- node = tanh(agg/deg + bias) -> g_seqA ----------------
__global__ void k_node(const float* __restrict__ gbias){
    int idx = blockIdx.x*256+threadIdx.x;
    int i = idx >> 8, j = idx & 255;
    g_seqA[idx] = ftanh(g_agg[idx]*__frcp_rn(g_deg[i]) + gbias[j]);
}

// ---------------- pack w_hh -> bf16x2, k-quad layout ----------------
__global__ void k_wtb(const float* __restrict__ whh, int layer){
    int idx = blockIdx.x*256+threadIdx.x;   // over 768*128
    int row = idx >> 7, q = idx & 127;
    int cq = q >> 2, j = q & 3;
    int k0 = cq*8 + 2*j;
    __nv_bfloat162 p = __floats2bfloat162_rn(whh[row*256 + k0], whh[row*256 + k0 + 1]);
    g_wb[layer][(cq*G3 + row)*4 + j] = *(unsigned*)&p;
}

// ---------------- GRU recurrence v7: local k-half in REGISTERS, peer half in smem ----------------
// Crossbar-bound fix: the 196KB/step weight stream through smem halves to 96KB (peer half);
// the local half (64 bf16x2 regs/thread) never touches the crossbar after init.
__global__ void __launch_bounds__(384) __cluster_dims__(2,1,1)
k_gru(const float* __restrict__ bhh, int osel, int layer){
    extern __shared__ unsigned sbw[];                // [16*384*4] = 98304 B (peer half only)
    __shared__ __align__(16) float h[2][HID];
    __shared__ float gh[3][128];
    __shared__ __align__(8) uint64_t mbar;
    int bx = blockIdx.x;
    int g = bx >> 1, rank = bx & 1;
    int tid = threadIdx.x;
    int band = tid >> 7, idx = tid & 127;
    int row = band*256 + rank*128 + idx;
    int u = rank*128 + idx;
    float* seqout = osel ? g_seqB : g_seqA;
    const unsigned* wl = g_wb[layer];

    uint32_t mbl = (uint32_t)__cvta_generic_to_shared(&mbar);
    uint32_t mbr;
    asm("mapa.shared::cluster.u32 %0, %1, %2;" : "=r"(mbr) : "r"(mbl), "r"(rank^1));
    if (tid == 0)
        asm volatile("mbarrier.init.shared.b64 [%0], 1;" :: "r"(mbl) : "memory");

    int cl0 = rank*16;          // k-quads covering locally-computed h (registers)
    int cp0 = (rank^1)*16;      // k-quads covering peer-delivered h (smem)

    // local half -> registers (64 x uint32 bf16x2)
    uint32_t wreg[64];
#pragma unroll
    for (int c=0; c<16; c++){
        uint4 wq = *(const uint4*)&wl[((cl0+c)*G3 + row)*4];
        wreg[c*4+0]=wq.x; wreg[c*4+1]=wq.y; wreg[c*4+2]=wq.z; wreg[c*4+3]=wq.w;
    }
    // peer half -> smem
#pragma unroll 4
    for (int c=0; c<16; c++)
        *(uint4*)&sbw[(c*384 + tid)*4] = *(const uint4*)&wl[((cp0+c)*G3 + row)*4];
    if (tid < HID) h[0][tid] = 0.f;
    float bb = bhh[row];
    const float* xpr = &g_xp[(size_t)g*256*G3];
    asm volatile("barrier.cluster.arrive.aligned;" ::: "memory");
    asm volatile("barrier.cluster.wait.aligned;"  ::: "memory");

    int ph = 0;
    for (int s=0; s<256; s++){
        int rp = s & 1, wp = rp ^ 1;
        float x0=0.f, x1=0.f, x2=0.f;
        if (band == 0){
            const float* xr = &xpr[(size_t)s*G3];
            x0 = xr[u]; x1 = xr[256+u]; x2 = xr[512+u];
        }
        const float* hp = h[rp];
        float a0=0.f, a1=0.f, a2=0.f, a3=0.f;
        // local half from registers (h computed locally last step)
#pragma unroll
        for (int c=0; c<16; c++){
            uint32_t wx=wreg[c*4], wy=wreg[c*4+1], wz=wreg[c*4+2], ww=wreg[c*4+3];
            float4 hA = *(const float4*)&hp[(cl0+c)*8];
            float4 hB = *(const float4*)&hp[(cl0+c)*8 + 4];
            a0 += __uint_as_float(wx << 16)         * hA.x;
            a1 += __uint_as_float(wx & 0xffff0000u) * hA.y;
            a2 += __uint_as_float(wy << 16)         * hA.z;
            a3 += __uint_as_float(wy & 0xffff0000u) * hA.w;
            a0 += __uint_as_float(wz << 16)         * hB.x;
            a1 += __uint_as_float(wz & 0xffff0000u) * hB.y;
            a2 += __uint_as_float(ww << 16)         * hB.z;
            a3 += __uint_as_float(ww & 0xffff0000u) * hB.w;
        }
        if (s > 0){
            unsigned done = 0;
            while (!done){
                asm volatile("{\n\t.reg .pred p;\n\t"
                    "mbarrier.try_wait.parity.acquire.cluster.shared::cta.b64 p, [%1], %2, 0x989680;\n\t"
                    "selp.b32 %0, 1, 0, p;\n\t}"
                    : "=r"(done) : "r"(mbl), "r"((unsigned)ph) : "memory");
            }
            ph ^= 1;
        }
        // peer half from smem (h delivered via DSMEM)
#pragma unroll 4
        for (int c=0; c<16; c++){
            uint4  wq = *(const uint4*)&sbw[(c*384 + tid)*4];
            float4 hA = *(const float4*)&hp[(cp0+c)*8];
            float4 hB = *(const float4*)&hp[(cp0+c)*8 + 4];
            a0 += __uint_as_float(wq.x << 16)         * hA.x;
            a1 += __uint_as_float(wq.x & 0xffff0000u) * hA.y;
            a2 += __uint_as_float(wq.y << 16)         * hA.z;
            a3 += __uint_as_float(wq.y & 0xffff0000u) * hA.w;
            a0 += __uint_as_float(wq.z << 16)         * hB.x;
            a1 += __uint_as_float(wq.z & 0xffff0000u) * hB.y;
            a2 += __uint_as_float(wq.w << 16)         * hB.z;
            a3 += __uint_as_float(wq.w & 0xffff0000u) * hB.w;
        }
        gh[band][idx] = a0 + a1 + a2 + a3 + bb;
        __syncthreads();
        if (band == 0){
            float r = fsig(x0 + gh[0][idx]);
            float z = fsig(x1 + gh[1][idx]);
            float n = ftanh(x2 + r*gh[2][idx]);
            float hn = (1.f - z)*n + z*hp[u];
            h[wp][u] = hn;
            uint32_t la = (uint32_t)__cvta_generic_to_shared(&h[wp][u]);
            uint32_t ra;
            asm("mapa.shared::cluster.u32 %0, %1, %2;" : "=r"(ra) : "r"(la), "r"(rank^1));
            asm volatile("st.shared::cluster.f32 [%0], %1;" :: "r"(ra), "f"(hn));
            seqout[(size_t)(g*256+s)*HID + u] = hn;
        }
        __syncthreads();   // all band0 local+remote stores issued before signal
        if (tid == 0 && s < 255)
            asm volatile("mbarrier.arrive.release.cluster.shared::cluster.b64 _, [%0];"
                         :: "r"(mbr) : "memory");
    }
    if (band == 0) g_ht[layer*NN_TOT + g*HID + u] = h[0][u];  // step 255 wrote wp=0
    asm volatile("barrier.cluster.arrive.aligned;" ::: "memory");
    asm volatile("barrier.cluster.wait.aligned;"  ::: "memory");
}

// ---------------- pooling + linear + softmax ----------------
__global__ void __launch_bounds__(256) k_final(const float* __restrict__ linW,
                                               const float* __restrict__ linb,
                                               float* __restrict__ out){
    __shared__ float r0[256], r1[256];
    int g = blockIdx.x, j = threadIdx.x;
    float mx = -1e30f, sm = 0.f;
    const float* seq = &g_seqB[(size_t)g*256*HID];
    for (int s=0;s<256;s++){
        float v = seq[(size_t)s*HID + j];
        mx = fmaxf(mx, v); sm += v;
    }
    float avg = sm * (1.0f/256.0f);
    float h0 = g_ht[0*NN_TOT + g*HID + j];
    float h1 = g_ht[1*NN_TOT + g*HID + j];
    float h2 = g_ht[2*NN_TOT + g*HID + j];
    float p0 = h0*linW[j] + h1*linW[256+j] + h2*linW[512+j] + mx*linW[768+j] + avg*linW[1024+j];
    float p1 = h0*linW[1280+j] + h1*linW[1536+j] + h2*linW[1792+j] + mx*linW[2048+j] + avg*linW[2304+j];
    r0[j] = p0; r1[j] = p1;
    __syncthreads();
    for (int stp=128; stp>0; stp>>=1){
        if (j < stp){ r0[j]+=r0[j+stp]; r1[j]+=r1[j+stp]; }
        __syncthreads();
    }
    if (j == 0){
        float l0 = r0[0] + linb[0], l1 = r1[0] + linb[1];
        float m = fmaxf(l0,l1);
        float e0 = expf(l0-m), e1 = expf(l1-m);
        float inv = 1.0f/(e0+e1);
        out[g*2+0] = e0*inv;
        out[g*2+1] = e1*inv;
    }
}

// ---------------- launch ----------------
extern "C" void kernel_launch(void* const* d_in, const int* in_sizes, int n_in,
                              void* d_out, int out_size){
    const float* x      = (const float*)d_in[0];
    const float* eattr  = (const float*)d_in[1];
    const int*   eidx   = (const int*)  d_in[2];
    const float* WA     = (const float*)d_in[3];
    const float* WB     = (const float*)d_in[4];
    const float* gbias  = (const float*)d_in[5];
    const float* wih[3] = {(const float*)d_in[6],  (const float*)d_in[10], (const float*)d_in[14]};
    const float* whh[3] = {(const float*)d_in[7],  (const float*)d_in[11], (const float*)d_in[15]};
    const float* bih[3] = {(const float*)d_in[8],  (const float*)d_in[12], (const float*)d_in[16]};
    const float* bhh[3] = {(const float*)d_in[9],  (const float*)d_in[13], (const float*)d_in[17]};
    const float* linW   = (const float*)d_in[18];
    const float* linb   = (const float*)d_in[19];
    float* out = (float*)d_out;

    size_t edge_smem = (64*256 + 8*64 + 8)*sizeof(float) + 16*sizeof(int) + 64;
    size_t gru_smem  = (size_t)16*384*4*sizeof(unsigned);   // 98304 B
    cudaFuncSetAttribute(k_edge, cudaFuncAttributeMaxDynamicSharedMemorySize, (int)edge_smem);
    cudaFuncSetAttribute(k_gru,  cudaFuncAttributeMaxDynamicSharedMemorySize, (int)gru_smem);

    k_deg_init<<<NN_TOT/256, 256>>>();
    k_deg_count<<<E_EDGES/256, 256>>>(eidx);
    k_dinv_beones<<<65, 256>>>(WB);
    // launch #4 (profiled slot): the Ax SGEMM
    k_gemm<<<dim3(OUTF/128, NN_TOT/128), 256>>>(x, 0, WA, nullptr, 0, OUTF);
    k_self<<<NN_TOT*OUTF/256, 256>>>();
    k_edge<<<1024, 256, edge_smem>>>(eattr, eidx, WB);
    k_node<<<NN_TOT*OUTF/256, 256>>>(gbias);
    for (int l=0;l<3;l++) k_wtb<<<G3*128/256, 256>>>(whh[l], l);

    const int insel[3]  = {0, 1, 0};
    const int outsel[3] = {1, 0, 1};
    for (int l=0;l<3;l++){
        k_gemm<<<dim3(G3/128, NN_TOT/128), 256>>>(nullptr, insel[l], wih[l], bih[l], 1, G3);
        k_gru<<<2*BGRAPH, 384, gru_smem>>>(bhh[l], outsel[l], l);
    }
    k_final<<<BGRAPH, 256>>>(linW, linb, out);
}

// round 16
// speedup vs baseline: 1.2760x; 1.1285x over previous
#include <cuda_runtime.h>
#include <cuda_bf16.h>
#include <cstdint>
#include <math.h>

#define BGRAPH 64
#define NNODE  256
#define FIN    256
#define OUTF   256
#define DEP    64
#define HID    256
#define G3     768
#define E_EDGES 262144
#define NN_TOT  16384
#define CQ     32

// ---------------- device scratch (accessed ONLY via symbol inside kernels) ----------------
__device__ __align__(16) float    g_deg [NN_TOT];
__device__ __align__(16) float    g_dinv[NN_TOT];
__device__ __align__(16) float    g_beones[OUTF];
__device__ __align__(16) float    g_Ax  [NN_TOT*OUTF];
__device__ __align__(16) float    g_agg [NN_TOT*OUTF];
__device__ __align__(16) float    g_seqA[NN_TOT*OUTF];
__device__ __align__(16) float    g_seqB[NN_TOT*OUTF];
__device__ __align__(16) float    g_xp  [NN_TOT*G3];
__device__ __align__(16) unsigned g_wb  [3][CQ*G3*4];  // bf16x2-packed w_hh
__device__ __align__(16) float    g_ht  [3*BGRAPH*HID];

// fast gates (ex2.approx-based, rel err ~1e-6)
__device__ __forceinline__ float fsig(float x){
    return __fdividef(1.0f, 1.0f + __expf(-x));
}
__device__ __forceinline__ float ftanh(float x){
    float x2 = fminf(fmaxf(2.0f*x, -30.0f), 30.0f);
    float e2 = __expf(x2);
    return __fdividef(e2 - 1.0f, e2 + 1.0f);
}
__device__ __forceinline__ uint32_t f2tf32(float f){
    uint32_t r;
    asm("cvt.rna.tf32.f32 %0, %1;" : "=r"(r) : "f"(f));
    return r;
}

// ---------------- degree ----------------
__global__ void k_deg_init(){ g_deg[blockIdx.x*256+threadIdx.x] = 1.0f; }
__global__ void k_deg_count(const int* __restrict__ eidx){
    int e = blockIdx.x*256+threadIdx.x;
    atomicAdd(&g_deg[eidx[E_EDGES+e]], 1.0f);
}
__global__ void k_dinv_beones(const float* __restrict__ WB){
    if (blockIdx.x < 64){
        int i = blockIdx.x*256+threadIdx.x;
        g_dinv[i] = rsqrtf(g_deg[i]);
    } else {
        int j = threadIdx.x; float s = 0.f;
        for (int k=0;k<DEP;k++) s += WB[j*DEP+k];
        g_beones[j] = s;
    }
}

// ---------------- GEMM v3: tf32 mma.sync, 128x128 CTA tile, warp 32x64 ----------------
// C[m][n] = sum_k A[m][k]*B[n][k] (+bias[n]); K=256. A row-major (k contig), B row-major
// over n (k contig) == col-major K x N, matching mma .row.col directly.
__global__ void __launch_bounds__(256) k_gemm(const float* __restrict__ Aext, int asel,
                                              const float* __restrict__ B,
                                              const float* __restrict__ bias,
                                              int csel, int N){
    const float* A = Aext ? Aext : (asel == 0 ? (const float*)g_seqA : (const float*)g_seqB);
    float* C = (csel == 0) ? g_Ax : g_xp;
    const int K = 256;
    __shared__ uint32_t As[128*36];   // stride 36: bank = (g*4+tig)%32, conflict-free frags
    __shared__ uint32_t Bs[128*36];
    int bm = blockIdx.y*128, bn = blockIdx.x*128;
    int t = threadIdx.x;
    int wid = t >> 5, lane = t & 31;
    int wm = (wid & 3)*32;        // warp m offset: 0,32,64,96
    int wn = (wid >> 2)*64;       // warp n offset: 0,64
    int g  = lane >> 2, tig = lane & 3;

    float d[16][4];
#pragma unroll
    for (int i=0;i<16;i++)
#pragma unroll
        for (int j=0;j<4;j++) d[i][j]=0.f;

    int r  = t >> 1;
    int cb = (t & 1)*16;
    for (int k0=0; k0<K; k0+=32){
        float4 av[4], bv[4];
#pragma unroll
        for (int i=0;i<4;i++){
            av[i] = *(const float4*)&A[(size_t)(bm+r)*K + k0 + cb + i*4];
            bv[i] = *(const float4*)&B[(size_t)(bn+r)*K + k0 + cb + i*4];
        }
        __syncthreads();
#pragma unroll
        for (int i=0;i<4;i++){
            As[r*36 + cb + i*4 + 0] = f2tf32(av[i].x);
            As[r*36 + cb + i*4 + 1] = f2tf32(av[i].y);
            As[r*36 + cb + i*4 + 2] = f2tf32(av[i].z);
            As[r*36 + cb + i*4 + 3] = f2tf32(av[i].w);
            Bs[r*36 + cb + i*4 + 0] = f2tf32(bv[i].x);
            Bs[r*36 + cb + i*4 + 1] = f2tf32(bv[i].y);
            Bs[r*36 + cb + i*4 + 2] = f2tf32(bv[i].z);
            Bs[r*36 + cb + i*4 + 3] = f2tf32(bv[i].w);
        }
        __syncthreads();
#pragma unroll
        for (int ks=0; ks<4; ks++){
            int kb = ks*8;
            uint32_t af[2][4];
#pragma unroll
            for (int mt=0; mt<2; mt++){
                int row = wm + mt*16 + g;
                af[mt][0] = As[row*36      + kb + tig];
                af[mt][1] = As[(row+8)*36  + kb + tig];
                af[mt][2] = As[row*36      + kb + tig + 4];
                af[mt][3] = As[(row+8)*36  + kb + tig + 4];
            }
            uint32_t bf[8][2];
#pragma unroll
            for (int nt=0; nt<8; nt++){
                int col = wn + nt*8 + g;
                bf[nt][0] = Bs[col*36 + kb + tig];
                bf[nt][1] = Bs[col*36 + kb + tig + 4];
            }
#pragma unroll
            for (int mt=0; mt<2; mt++)
#pragma unroll
                for (int nt=0; nt<8; nt++){
                    float* dd = d[mt*8+nt];
                    asm volatile(
                        "mma.sync.aligned.m16n8k8.row.col.f32.tf32.tf32.f32 "
                        "{%0,%1,%2,%3}, {%4,%5,%6,%7}, {%8,%9}, {%0,%1,%2,%3};"
                        : "+f"(dd[0]), "+f"(dd[1]), "+f"(dd[2]), "+f"(dd[3])
                        : "r"(af[mt][0]), "r"(af[mt][1]), "r"(af[mt][2]), "r"(af[mt][3]),
                          "r"(bf[nt][0]), "r"(bf[nt][1]));
                }
        }
    }
#pragma unroll
    for (int mt=0; mt<2; mt++)
#pragma unroll
        for (int nt=0; nt<8; nt++){
            float* dd = d[mt*8+nt];
            int row0 = bm + wm + mt*16 + g;
            int col  = bn + wn + nt*8 + tig*2;
            float b0 = bias ? bias[col]   : 0.f;
            float b1 = bias ? bias[col+1] : 0.f;
            float2 o0 = make_float2(dd[0]+b0, dd[1]+b1);
            float2 o1 = make_float2(dd[2]+b0, dd[3]+b1);
            *(float2*)&C[(size_t)row0*N + col]     = o0;
            *(float2*)&C[(size_t)(row0+8)*N + col] = o1;
        }
}

// ---------------- GCN self-loop init of agg ----------------
__global__ void k_self(){
    int idx = blockIdx.x*256+threadIdx.x;
    int i = idx >> 8, j = idx & 255;
    float dv = g_dinv[i];
    g_agg[idx] = dv*dv*ftanh(g_Ax[idx]*g_beones[j]);
}

// ---------------- GCN edge aggregation (global atomics) ----------------
__global__ void __launch_bounds__(256) k_edge(const float* __restrict__ eattr,
                                              const int*   __restrict__ eidx,
                                              const float* __restrict__ WB){
    extern __shared__ float sh[];
    float* WBt   = sh;              // [64][256] k-major
    float* ea_sh = WBt + 64*256;    // [8][64]
    float* snorm = ea_sh + 8*64;    // [8]
    int*   ssrc  = (int*)(snorm+8); // [8]
    int*   sdst  = ssrc + 8;        // [8]

    int t = threadIdx.x;
    for (int idx=t; idx<64*256; idx+=256){
        int j = idx & 255, k = idx >> 8;
        WBt[idx] = WB[j*DEP + k];
    }
    int w = t >> 5, lane = t & 31;
    int base = blockIdx.x*256;

    for (int b=0;b<32;b++){
        __syncthreads();
        int e0 = base + b*8;
        if (t < 8){
            int e = e0 + t;
            int s = eidx[e], d = eidx[E_EDGES+e];
            ssrc[t]=s; sdst[t]=d; snorm[t]=g_dinv[s]*g_dinv[d];
        }
        {
            int e = t >> 5, k2 = (t & 31)*2;
            *(float2*)&ea_sh[e*64+k2] = *(const float2*)&eattr[(size_t)(e0+e)*DEP + k2];
        }
        __syncthreads();

        int   src = ssrc[w], dst = sdst[w];
        float nr  = snorm[w];
        const float* ea = &ea_sh[w*64];
#pragma unroll
        for (int p=0;p<2;p++){
            int j = p*128 + lane*4;
            float4 acc = make_float4(0.f,0.f,0.f,0.f);
#pragma unroll 8
            for (int k=0;k<64;k++){
                float a = ea[k];
                float4 wv = *(const float4*)&WBt[k*256 + j];
                acc.x += a*wv.x; acc.y += a*wv.y; acc.z += a*wv.z; acc.w += a*wv.w;
            }
            float4 ax = *(const float4*)&g_Ax[(size_t)src*256 + j];
            float* ag = &g_agg[(size_t)dst*256 + j];
            atomicAdd(&ag[0], nr*ftanh(ax.x*acc.x));
            atomicAdd(&ag[1], nr*ftanh(ax.y*acc.y));
            atomicAdd(&ag[2], nr*ftanh(ax.z*acc.z));
            atomicAdd(&ag[3], nr*ftanh(ax.w*acc.w));
        }
    }
}

// ---------------- node = tanh(agg/deg + bias) -> g_seqA ----------------
__global__ void k_node(const float* __restrict__ gbias){
    int idx = blockIdx.x*256+threadIdx.x;
    int i = idx >> 8, j = idx & 255;
    g_seqA[idx] = ftanh(g_agg[idx]*__frcp_rn(g_deg[i]) + gbias[j]);
}

// ---------------- pack w_hh -> bf16x2, k-quad layout ----------------
__global__ void k_wtb(const float* __restrict__ whh, int layer){
    int idx = blockIdx.x*256+threadIdx.x;   // over 768*128
    int row = idx >> 7, q = idx & 127;
    int cq = q >> 2, j = q & 3;
    int k0 = cq*8 + 2*j;
    __nv_bfloat162 p = __floats2bfloat162_rn(whh[row*256 + k0], whh[row*256 + k0 + 1]);
    g_wb[layer][(cq*G3 + row)*4 + j] = *(unsigned*)&p;
}

// ---------------- GRU recurrence v7: local k-half in REGISTERS, peer half in smem ----------------
__global__ void __launch_bounds__(384) __cluster_dims__(2,1,1)
k_gru(const float* __restrict__ bhh, int osel, int layer){
    extern __shared__ unsigned sbw[];                // [16*384*4] = 98304 B (peer half only)
    __shared__ __align__(16) float h[2][HID];
    __shared__ float gh[3][128];
    __shared__ __align__(8) uint64_t mbar;
    int bx = blockIdx.x;
    int g = bx >> 1, rank = bx & 1;
    int tid = threadIdx.x;
    int band = tid >> 7, idx = tid & 127;
    int row = band*256 + rank*128 + idx;
    int u = rank*128 + idx;
    float* seqout = osel ? g_seqB : g_seqA;
    const unsigned* wl = g_wb[layer];

    uint32_t mbl = (uint32_t)__cvta_generic_to_shared(&mbar);
    uint32_t mbr;
    asm("mapa.shared::cluster.u32 %0, %1, %2;" : "=r"(mbr) : "r"(mbl), "r"(rank^1));
    if (tid == 0)
        asm volatile("mbarrier.init.shared.b64 [%0], 1;" :: "r"(mbl) : "memory");

    int cl0 = rank*16;          // k-quads covering locally-computed h (registers)
    int cp0 = (rank^1)*16;      // k-quads covering peer-delivered h (smem)

    uint32_t wreg[64];
#pragma unroll
    for (int c=0; c<16; c++){
        uint4 wq = *(const uint4*)&wl[((cl0+c)*G3 + row)*4];
        wreg[c*4+0]=wq.x; wreg[c*4+1]=wq.y; wreg[c*4+2]=wq.z; wreg[c*4+3]=wq.w;
    }
#pragma unroll 4
    for (int c=0; c<16; c++)
        *(uint4*)&sbw[(c*384 + tid)*4] = *(const uint4*)&wl[((cp0+c)*G3 + row)*4];
    if (tid < HID) h[0][tid] = 0.f;
    float bb = bhh[row];
    const float* xpr = &g_xp[(size_t)g*256*G3];
    asm volatile("barrier.cluster.arrive.aligned;" ::: "memory");
    asm volatile("barrier.cluster.wait.aligned;"  ::: "memory");

    int ph = 0;
    for (int s=0; s<256; s++){
        int rp = s & 1, wp = rp ^ 1;
        float x0=0.f, x1=0.f, x2=0.f;
        if (band == 0){
            const float* xr = &xpr[(size_t)s*G3];
            x0 = xr[u]; x1 = xr[256+u]; x2 = xr[512+u];
        }
        const float* hp = h[rp];
        float a0=0.f, a1=0.f, a2=0.f, a3=0.f;
#pragma unroll
        for (int c=0; c<16; c++){
            uint32_t wx=wreg[c*4], wy=wreg[c*4+1], wz=wreg[c*4+2], ww=wreg[c*4+3];
            float4 hA = *(const float4*)&hp[(cl0+c)*8];
            float4 hB = *(const float4*)&hp[(cl0+c)*8 + 4];
            a0 += __uint_as_float(wx << 16)         * hA.x;
            a1 += __uint_as_float(wx & 0xffff0000u) * hA.y;
            a2 += __uint_as_float(wy << 16)         * hA.z;
            a3 += __uint_as_float(wy & 0xffff0000u) * hA.w;
            a0 += __uint_as_float(wz << 16)         * hB.x;
            a1 += __uint_as_float(wz & 0xffff0000u) * hB.y;
            a2 += __uint_as_float(ww << 16)         * hB.z;
            a3 += __uint_as_float(ww & 0xffff0000u) * hB.w;
        }
        if (s > 0){
            unsigned done = 0;
            while (!done){
                asm volatile("{\n\t.reg .pred p;\n\t"
                    "mbarrier.try_wait.parity.acquire.cluster.shared::cta.b64 p, [%1], %2, 0x989680;\n\t"
                    "selp.b32 %0, 1, 0, p;\n\t}"
                    : "=r"(done) : "r"(mbl), "r"((unsigned)ph) : "memory");
            }
            ph ^= 1;
        }
#pragma unroll 4
        for (int c=0; c<16; c++){
            uint4  wq = *(const uint4*)&sbw[(c*384 + tid)*4];
            float4 hA = *(const float4*)&hp[(cp0+c)*8];
            float4 hB = *(const float4*)&hp[(cp0+c)*8 + 4];
            a0 += __uint_as_float(wq.x << 16)         * hA.x;
            a1 += __uint_as_float(wq.x & 0xffff0000u) * hA.y;
            a2 += __uint_as_float(wq.y << 16)         * hA.z;
            a3 += __uint_as_float(wq.y & 0xffff0000u) * hA.w;
            a0 += __uint_as_float(wq.z << 16)         * hB.x;
            a1 += __uint_as_float(wq.z & 0xffff0000u) * hB.y;
            a2 += __uint_as_float(wq.w << 16)         * hB.z;
            a3 += __uint_as_float(wq.w & 0xffff0000u) * hB.w;
        }
        gh[band][idx] = a0 + a1 + a2 + a3 + bb;
        __syncthreads();
        if (band == 0){
            float r = fsig(x0 + gh[0][idx]);
            float z = fsig(x1 + gh[1][idx]);
            float n = ftanh(x2 + r*gh[2][idx]);
            float hn = (1.f - z)*n + z*hp[u];
            h[wp][u] = hn;
            uint32_t la = (uint32_t)__cvta_generic_to_shared(&h[wp][u]);
            uint32_t ra;
            asm("mapa.shared::cluster.u32 %0, %1, %2;" : "=r"(ra) : "r"(la), "r"(rank^1));
            asm volatile("st.shared::cluster.f32 [%0], %1;" :: "r"(ra), "f"(hn));
            seqout[(size_t)(g*256+s)*HID + u] = hn;
        }
        __syncthreads();
        if (tid == 0 && s < 255)
            asm volatile("mbarrier.arrive.release.cluster.shared::cluster.b64 _, [%0];"
                         :: "r"(mbr) : "memory");
    }
    if (band == 0) g_ht[layer*NN_TOT + g*HID + u] = h[0][u];
    asm volatile("barrier.cluster.arrive.aligned;" ::: "memory");
    asm volatile("barrier.cluster.wait.aligned;"  ::: "memory");
}

// ---------------- pooling + linear + softmax ----------------
__global__ void __launch_bounds__(256) k_final(const float* __restrict__ linW,
                                               const float* __restrict__ linb,
                                               float* __restrict__ out){
    __shared__ float r0[256], r1[256];
    int g = blockIdx.x, j = threadIdx.x;
    float mx = -1e30f, sm = 0.f;
    const float* seq = &g_seqB[(size_t)g*256*HID];
    for (int s=0;s<256;s++){
        float v = seq[(size_t)s*HID + j];
        mx = fmaxf(mx, v); sm += v;
    }
    float avg = sm * (1.0f/256.0f);
    float h0 = g_ht[0*NN_TOT + g*HID + j];
    float h1 = g_ht[1*NN_TOT + g*HID + j];
    float h2 = g_ht[2*NN_TOT + g*HID + j];
    float p0 = h0*linW[j] + h1*linW[256+j] + h2*linW[512+j] + mx*linW[768+j] + avg*linW[1024+j];
    float p1 = h0*linW[1280+j] + h1*linW[1536+j] + h2*linW[1792+j] + mx*linW[2048+j] + avg*linW[2304+j];
    r0[j] = p0; r1[j] = p1;
    __syncthreads();
    for (int stp=128; stp>0; stp>>=1){
        if (j < stp){ r0[j]+=r0[j+stp]; r1[j]+=r1[j+stp]; }
        __syncthreads();
    }
    if (j == 0){
        float l0 = r0[0] + linb[0], l1 = r1[0] + linb[1];
        float m = fmaxf(l0,l1);
        float e0 = expf(l0-m), e1 = expf(l1-m);
        float inv = 1.0f/(e0+e1);
        out[g*2+0] = e0*inv;
        out[g*2+1] = e1*inv;
    }
}

// ---------------- launch ----------------
extern "C" void kernel_launch(void* const* d_in, const int* in_sizes, int n_in,
                              void* d_out, int out_size){
    const float* x      = (const float*)d_in[0];
    const float* eattr  = (const float*)d_in[1];
    const int*   eidx   = (const int*)  d_in[2];
    const float* WA     = (const float*)d_in[3];
    const float* WB     = (const float*)d_in[4];
    const float* gbias  = (const float*)d_in[5];
    const float* wih[3] = {(const float*)d_in[6],  (const float*)d_in[10], (const float*)d_in[14]};
    const float* whh[3] = {(const float*)d_in[7],  (const float*)d_in[11], (const float*)d_in[15]};
    const float* bih[3] = {(const float*)d_in[8],  (const float*)d_in[12], (const float*)d_in[16]};
    const float* bhh[3] = {(const float*)d_in[9],  (const float*)d_in[13], (const float*)d_in[17]};
    const float* linW   = (const float*)d_in[18];
    const float* linb   = (const float*)d_in[19];
    float* out = (float*)d_out;

    size_t edge_smem = (64*256 + 8*64 + 8)*sizeof(float) + 16*sizeof(int) + 64;
    size_t gru_smem  = (size_t)16*384*4*sizeof(unsigned);   // 98304 B
    cudaFuncSetAttribute(k_edge, cudaFuncAttributeMaxDynamicSharedMemorySize, (int)edge_smem);
    cudaFuncSetAttribute(k_gru,  cudaFuncAttributeMaxDynamicSharedMemorySize, (int)gru_smem);

    k_deg_init<<<NN_TOT/256, 256>>>();
    k_deg_count<<<E_EDGES/256, 256>>>(eidx);
    k_dinv_beones<<<65, 256>>>(WB);
    // launch #4 (profiled slot): the Ax GEMM (now tf32 mma)
    k_gemm<<<dim3(OUTF/128, NN_TOT/128), 256>>>(x, 0, WA, nullptr, 0, OUTF);
    k_self<<<NN_TOT*OUTF/256, 256>>>();
    k_edge<<<1024, 256, edge_smem>>>(eattr, eidx, WB);
    k_node<<<NN_TOT*OUTF/256, 256>>>(gbias);
    for (int l=0;l<3;l++) k_wtb<<<G3*128/256, 256>>>(whh[l], l);

    const int insel[3]  = {0, 1, 0};
    const int outsel[3] = {1, 0, 1};
    for (int l=0;l<3;l++){
        k_gemm<<<dim3(G3/128, NN_TOT/128), 256>>>(nullptr, insel[l], wih[l], bih[l], 1, G3);
        k_gru<<<2*BGRAPH, 384, gru_smem>>>(bhh[l], outsel[l], l);
    }
    k_final<<<BGRAPH, 256>>>(linW, linb, out);
}